// round 8
// baseline (speedup 1.0000x reference)
#include <cuda_runtime.h>
#include <cstdint>
#include <math.h>

#define HIDDEN 1024
#define NH     16
#define HD     64
#define SEQ    2048
#define BATCH  2
#define MTOT   (BATCH*SEQ)   // 4096
#define WIN    128
#define QB     64

// ---------------- scratch (device globals) -------------------------------------
__device__ float g_Q[BATCH*NH*SEQ*HD];
__device__ float g_K[BATCH*NH*SEQ*HD];
__device__ float g_V[BATCH*NH*SEQ*HD];
__device__ float g_At[MTOT*HIDDEN];   // attention output (raw fp32)

// ---------------- helpers -------------------------------------------------------
__device__ __forceinline__ uint32_t smem_u32(const void* p) {
    uint32_t a;
    asm("{ .reg .u64 t; cvta.to.shared.u64 t, %1; cvt.u32.u64 %0, t; }" : "=r"(a) : "l"(p));
    return a;
}
__device__ __forceinline__ float tf32r(float x) {
    uint32_t y;
    asm("cvt.rna.tf32.f32 %0, %1;" : "=r"(y) : "f"(x));
    return __uint_as_float(y);
}
__device__ __forceinline__ void cp16(uint32_t dst, const float* src) {
    asm volatile("cp.async.cg.shared.global [%0], [%1], 16;" :: "r"(dst), "l"(src) : "memory");
}
__device__ __forceinline__ void cp16z(uint32_t dst, const float* src, int srcsz) {
    asm volatile("cp.async.cg.shared.global [%0], [%1], 16, %2;"
                 :: "r"(dst), "l"(src), "r"(srcsz) : "memory");
}
#define CP_COMMIT() asm volatile("cp.async.commit_group;" ::: "memory")
#define CP_WAIT1()  asm volatile("cp.async.wait_group 1;" ::: "memory")
#define CP_WAIT0()  asm volatile("cp.async.wait_group 0;" ::: "memory")

__device__ __forceinline__ void mma_tf32(float* d, const uint32_t* a, const uint32_t* b) {
    asm volatile("mma.sync.aligned.m16n8k8.row.col.f32.tf32.tf32.f32 "
        "{%0,%1,%2,%3}, {%4,%5,%6,%7}, {%8,%9}, {%0,%1,%2,%3};"
        : "+f"(d[0]), "+f"(d[1]), "+f"(d[2]), "+f"(d[3])
        : "r"(a[0]), "r"(a[1]), "r"(a[2]), "r"(a[3]), "r"(b[0]), "r"(b[1]));
}

// ---------------- tf32 GEMM: 128x128 tile, 64x32 warp tile, 2 CTAs/SM ------------
#define BM 128
#define BN 128
#define BK 32
#define STAGES 3
#define AS_STRIDE 36
#define BS_STRIDE 132
#define A_STAGE (BM*AS_STRIDE)             // 4608
#define B_STAGE (BK*BS_STRIDE)             // 4224
#define STAGE_FLOATS (A_STAGE + B_STAGE)   // 8832
#define GEMM_SMEM (STAGES*STAGE_FLOATS*4)  // 105984 B  (2 CTAs/SM)

__global__ __launch_bounds__(256, 2) void gemm_mma_kernel(
    const float* __restrict__ A,
    const float* __restrict__ W0, const float* __restrict__ W1, const float* __restrict__ W2,
    const float* __restrict__ bias0, const float* __restrict__ bias1, const float* __restrict__ bias2,
    float* __restrict__ out0, float* __restrict__ out1, float* __restrict__ out2,
    int mode)
{
    extern __shared__ float sm[];
    const int tid  = threadIdx.x;
    const int lane = tid & 31;
    const int wid  = tid >> 5;
    const int n0 = blockIdx.x * BN;
    const int m0 = blockIdx.y * BM;
    const int z  = blockIdx.z;

    const float* W    = (z == 0) ? W0 : (z == 1) ? W1 : W2;
    const float* bias = (z == 0) ? bias0 : (z == 1) ? bias1 : bias2;
    float* out        = (z == 0) ? out0 : (z == 1) ? out1 : out2;

    const int wm = (wid & 1) * 64;
    const int wn = (wid >> 1) * 32;

    float d[4][4][4];
#pragma unroll
    for (int mi = 0; mi < 4; mi++)
#pragma unroll
        for (int ni = 0; ni < 4; ni++)
#pragma unroll
            for (int c = 0; c < 4; c++) d[mi][ni][c] = 0.f;

    const uint32_t sb = smem_u32(sm);

    auto load_stage = [&](int kt, int s) {
        const uint32_t a_off = sb + (uint32_t)(s * STAGE_FLOATS) * 4u;
        const uint32_t b_off = a_off + A_STAGE * 4u;
        const float* Ag = A + (long)m0 * HIDDEN + kt * BK;
        const float* Wg = W + (long)(kt * BK) * HIDDEN + n0;
#pragma unroll
        for (int rep = 0; rep < 4; rep++) {
            int lin = rep * 256 + tid;
            int ar = lin >> 3, aq = lin & 7;
            cp16(a_off + (uint32_t)(ar * AS_STRIDE + aq * 4) * 4u,
                 Ag + (long)ar * HIDDEN + aq * 4);
            int br = lin >> 5, bq = lin & 31;
            cp16(b_off + (uint32_t)(br * BS_STRIDE + bq * 4) * 4u,
                 Wg + (long)br * HIDDEN + bq * 4);
        }
        CP_COMMIT();
    };

    load_stage(0, 0);
    load_stage(1, 1);

    const int lg = lane >> 2;
    const int lt = lane & 3;

    for (int kt = 0; kt < HIDDEN / BK; kt++) {
        const int s = kt % STAGES;
        CP_WAIT1();
        __syncthreads();
        if (kt + 2 < HIDDEN / BK) load_stage(kt + 2, (kt + 2) % STAGES);
        else CP_COMMIT();

        const float* As = sm + s * STAGE_FLOATS;
        const float* Bs = As + A_STAGE;

#pragma unroll
        for (int k8 = 0; k8 < 4; k8++) {
            const int kb = k8 * 8;
            uint32_t a[4][4];
#pragma unroll
            for (int mi = 0; mi < 4; mi++) {
                const float* ap = As + (wm + mi * 16 + lg) * AS_STRIDE + kb + lt;
                a[mi][0] = __float_as_uint(tf32r(ap[0]));
                a[mi][1] = __float_as_uint(tf32r(ap[8 * AS_STRIDE]));
                a[mi][2] = __float_as_uint(tf32r(ap[4]));
                a[mi][3] = __float_as_uint(tf32r(ap[8 * AS_STRIDE + 4]));
            }
#pragma unroll
            for (int ni = 0; ni < 4; ni++) {
                uint32_t bb[2];
                const float* bp = Bs + (kb + lt) * BS_STRIDE + wn + ni * 8 + lg;
                bb[0] = __float_as_uint(tf32r(bp[0]));
                bb[1] = __float_as_uint(tf32r(bp[4 * BS_STRIDE]));
#pragma unroll
                for (int mi = 0; mi < 4; mi++)
                    mma_tf32(d[mi][ni], a[mi], bb);
            }
        }
    }

#pragma unroll
    for (int mi = 0; mi < 4; mi++) {
#pragma unroll
        for (int rh = 0; rh < 2; rh++) {
            const int row = m0 + wm + mi * 16 + lg + rh * 8;
            const int bb = row >> 11;
            const int ss = row & (SEQ - 1);
#pragma unroll
            for (int ni = 0; ni < 4; ni++) {
                const int col = n0 + wn + ni * 8 + lt * 2;
                float2 v;
                v.x = d[mi][ni][rh * 2 + 0] + __ldg(&bias[col]);
                v.y = d[mi][ni][rh * 2 + 1] + __ldg(&bias[col + 1]);
                if (mode == 0) {
                    const int h  = col >> 6;
                    const int dd = col & 63;
                    *(float2*)&out[(((long)(bb * NH + h) * SEQ) + ss) * HD + dd] = v;
                } else {
                    *(float2*)&out[(long)row * HIDDEN + col] = v;
                }
            }
        }
    }
}

// ---------------- chunked attention (unchanged from R7) --------------------------
#define CH   160
#define SQ   68
#define SKN  68
#define SVC  72
#define SPC  164
#define SO   66
#define QS_OFF  0
#define KS_OFF  4352
#define VS_OFF  (KS_OFF + CH*SKN)
#define RED_OFF (VS_OFF + CH*SVC)
#define ATTN_FLOATS (RED_OFF + 128)
#define ATTN_SMEM (ATTN_FLOATS * 4)

__global__ __launch_bounds__(256, 2) void attn_mma_kernel(
    const float* __restrict__ Q, const float* __restrict__ K,
    const float* __restrict__ V, float* __restrict__ O)
{
    extern __shared__ float sm[];
    float* Qs = sm + QS_OFF;
    float* Ks = sm + KS_OFF;
    float* Vs = sm + VS_OFF;
    float* red = sm + RED_OFF;

    const int q0 = blockIdx.x * QB;
    const int h  = blockIdx.y;
    const int b  = blockIdx.z;
    const int tid = threadIdx.x;
    const long base = ((long)(b * NH + h)) * SEQ * HD;
    const float* Kb = K + base;
    const float* Vb = V + base;
    const float* Qb = Q + base;
    const int j0 = q0 - WIN;

    const uint32_t sb = smem_u32(sm);
    const int lane = tid & 31;
    const int wid  = tid >> 5;
    const int lg = lane >> 2;
    const int lt = lane & 3;
    const int wm = (wid & 3) * 16;
    const int half = wid >> 2;
    const int wn = half * 80;
    const float scale = 0.125f;

    for (int idx = tid; idx < 64 * 16; idx += 256) {
        int r = idx >> 4, c4 = (idx & 15) << 2;
        float4 v = *(const float4*)&Qb[(long)(q0 + r) * HD + c4];
        v.x = tf32r(v.x); v.y = tf32r(v.y); v.z = tf32r(v.z); v.w = tf32r(v.w);
        *(float4*)&Qs[r * SQ + c4] = v;
    }

    float o[8][4];
#pragma unroll
    for (int nt = 0; nt < 8; nt++) { o[nt][0] = 0.f; o[nt][1] = 0.f; o[nt][2] = 0.f; o[nt][3] = 0.f; }
    float sum0 = 0.f, sum1 = 0.f;

    const int r0 = q0 + wm + lg;
    const int r1 = r0 + 8;
    const int lo0 = ((r0 - WIN > 0) ? r0 - WIN : 0) - j0;
    const int hi0 = ((r0 + WIN < SEQ - 1) ? r0 + WIN : SEQ - 1) - j0;
    const int lo1 = ((r1 - WIN > 0) ? r1 - WIN : 0) - j0;
    const int hi1 = ((r1 + WIN < SEQ - 1) ? r1 + WIN : SEQ - 1) - j0;

    uint32_t a[8][4];
    bool afrag_loaded = false;

#pragma unroll
    for (int ch = 0; ch < 2; ch++) {
        const int cb = ch * CH;

        {
            const int rb = tid >> 4;
            const int cq = (tid & 15) << 2;
#pragma unroll
            for (int r10 = 0; r10 < 10; r10++) {
                const int jj = r10 * 16 + rb;
                const int j  = j0 + cb + jj;
                const int ok = (j >= 0 && j < SEQ) ? 16 : 0;
                cp16z(sb + (uint32_t)(KS_OFF + jj * SKN + cq) * 4u, Kb + (long)j * HD + cq, ok);
                cp16z(sb + (uint32_t)(VS_OFF + jj * SVC + cq) * 4u, Vb + (long)j * HD + cq, ok);
            }
            CP_COMMIT();
        }
        CP_WAIT0();
        __syncthreads();

        if (!afrag_loaded) {
            afrag_loaded = true;
#pragma unroll
            for (int k8 = 0; k8 < 8; k8++) {
                const float* ap = Qs + (wm + lg) * SQ + k8 * 8 + lt;
                a[k8][0] = __float_as_uint(ap[0]);
                a[k8][1] = __float_as_uint(ap[8 * SQ]);
                a[k8][2] = __float_as_uint(ap[4]);
                a[k8][3] = __float_as_uint(ap[8 * SQ + 4]);
            }
        }

        float c[10][4];
#pragma unroll
        for (int nt = 0; nt < 10; nt++) {
            c[nt][0] = 0.f; c[nt][1] = 0.f; c[nt][2] = 0.f; c[nt][3] = 0.f;
            const int key = wn + nt * 8 + lg;
            const float* kp = Ks + key * SKN + lt;
#pragma unroll
            for (int k8 = 0; k8 < 8; k8++) {
                uint32_t bb[2];
                bb[0] = __float_as_uint(tf32r(kp[k8 * 8]));
                bb[1] = __float_as_uint(tf32r(kp[k8 * 8 + 4]));
                mma_tf32(c[nt], a[k8], bb);
            }
        }

#pragma unroll
        for (int nt = 0; nt < 10; nt++) {
            const int jw = cb + wn + nt * 8 + 2 * lt;
            float p0 = (jw     >= lo0 && jw     <= hi0) ? tf32r(__expf(c[nt][0] * scale)) : 0.f;
            float p1 = (jw + 1 >= lo0 && jw + 1 <= hi0) ? tf32r(__expf(c[nt][1] * scale)) : 0.f;
            float p2 = (jw     >= lo1 && jw     <= hi1) ? tf32r(__expf(c[nt][2] * scale)) : 0.f;
            float p3 = (jw + 1 >= lo1 && jw + 1 <= hi1) ? tf32r(__expf(c[nt][3] * scale)) : 0.f;
            c[nt][0] = p0; c[nt][1] = p1; c[nt][2] = p2; c[nt][3] = p3;
            sum0 += p0 + p1;
            sum1 += p2 + p3;
        }

        __syncthreads();

        float* Ps = Ks;
#pragma unroll
        for (int nt = 0; nt < 10; nt++) {
            const int col = wn + nt * 8 + 2 * lt;
            *(float2*)&Ps[(wm + lg) * SPC + col]     = make_float2(c[nt][0], c[nt][1]);
            *(float2*)&Ps[(wm + lg + 8) * SPC + col] = make_float2(c[nt][2], c[nt][3]);
        }
        __syncthreads();

#pragma unroll
        for (int k8 = 0; k8 < 10; k8++) {
            const int kk = wn + k8 * 8;
            uint32_t a2[4];
            const float* ap = Ps + (wm + lg) * SPC + kk + lt;
            a2[0] = __float_as_uint(ap[0]);
            a2[1] = __float_as_uint(ap[8 * SPC]);
            a2[2] = __float_as_uint(ap[4]);
            a2[3] = __float_as_uint(ap[8 * SPC + 4]);
#pragma unroll
            for (int nt = 0; nt < 8; nt++) {
                uint32_t bb[2];
                const float* bp = Vs + (kk + lt) * SVC + nt * 8 + lg;
                bb[0] = __float_as_uint(bp[0]);
                bb[1] = __float_as_uint(bp[4 * SVC]);
                mma_tf32(o[nt], a2, bb);
            }
        }
        __syncthreads();
    }

    sum0 += __shfl_xor_sync(0xffffffffu, sum0, 1);
    sum0 += __shfl_xor_sync(0xffffffffu, sum0, 2);
    sum1 += __shfl_xor_sync(0xffffffffu, sum1, 1);
    sum1 += __shfl_xor_sync(0xffffffffu, sum1, 2);
    if (lt == 0) {
        red[half * 64 + wm + lg]     = sum0;
        red[half * 64 + wm + lg + 8] = sum1;
    }

    float* obuf = Qs;
    if (half == 0) {
#pragma unroll
        for (int nt = 0; nt < 8; nt++) {
            const int col = nt * 8 + 2 * lt;
            *(float2*)&obuf[(wm + lg) * SO + col]     = make_float2(o[nt][0], o[nt][1]);
            *(float2*)&obuf[(wm + lg + 8) * SO + col] = make_float2(o[nt][2], o[nt][3]);
        }
    }
    __syncthreads();
    if (half == 1) {
        const float inv0 = 1.f / (red[wm + lg] + red[64 + wm + lg]);
        const float inv1 = 1.f / (red[wm + lg + 8] + red[64 + wm + lg + 8]);
        const long ob0 = ((long)(b * SEQ + r0)) * HIDDEN + h * HD;
        const long ob1 = ((long)(b * SEQ + r1)) * HIDDEN + h * HD;
#pragma unroll
        for (int nt = 0; nt < 8; nt++) {
            const int col = nt * 8 + 2 * lt;
            float2 u0 = *(const float2*)&obuf[(wm + lg) * SO + col];
            float2 u1 = *(const float2*)&obuf[(wm + lg + 8) * SO + col];
            float2 w0, w1;
            w0.x = (o[nt][0] + u0.x) * inv0;
            w0.y = (o[nt][1] + u0.y) * inv0;
            w1.x = (o[nt][2] + u1.x) * inv1;
            w1.y = (o[nt][3] + u1.y) * inv1;
            *(float2*)&O[ob0 + col] = w0;
            *(float2*)&O[ob1 + col] = w1;
        }
    }
}

// ---------------- launcher --------------------------------------------------------
extern "C" void kernel_launch(void* const* d_in, const int* in_sizes, int n_in,
                              void* d_out, int out_size)
{
    const float* x  = (const float*)d_in[0];
    const float* wq = (const float*)d_in[1];
    const float* bq = (const float*)d_in[2];
    const float* wk = (const float*)d_in[3];
    const float* bk = (const float*)d_in[4];
    const float* wv = (const float*)d_in[5];
    const float* bv = (const float*)d_in[6];
    const float* wo = (const float*)d_in[7];
    const float* bo = (const float*)d_in[8];

    float *gq, *gk, *gv, *gat;
    cudaGetSymbolAddress((void**)&gq,  g_Q);
    cudaGetSymbolAddress((void**)&gk,  g_K);
    cudaGetSymbolAddress((void**)&gv,  g_V);
    cudaGetSymbolAddress((void**)&gat, g_At);

    cudaFuncSetAttribute(gemm_mma_kernel,
                         cudaFuncAttributeMaxDynamicSharedMemorySize, GEMM_SMEM);
    cudaFuncSetAttribute(attn_mma_kernel,
                         cudaFuncAttributeMaxDynamicSharedMemorySize, ATTN_SMEM);

    {   // fused QKV projections straight from raw inputs (in-register rounding)
        dim3 g(HIDDEN / BN, MTOT / BM, 3);
        gemm_mma_kernel<<<g, 256, GEMM_SMEM>>>(x, wq, wk, wv,
                                               bq, bk, bv, gq, gk, gv, 0);
    }
    {   // chunked MMA attention -> raw fp32 into g_At
        dim3 ga(SEQ / QB, NH, BATCH);
        attn_mma_kernel<<<ga, 256, ATTN_SMEM>>>(gq, gk, gv, gat);
    }
    {   // output projection
        dim3 g(HIDDEN / BN, MTOT / BM, 1);
        gemm_mma_kernel<<<g, 256, GEMM_SMEM>>>(gat, wo, wo, wo,
                                               bo, bo, bo, (float*)d_out,
                                               (float*)d_out, (float*)d_out, 1);
    }
}

// round 9
// speedup vs baseline: 1.1041x; 1.1041x over previous
#include <cuda_runtime.h>
#include <cstdint>
#include <math.h>

#define HIDDEN 1024
#define NH     16
#define HD     64
#define SEQ    2048
#define BATCH  2
#define MTOT   (BATCH*SEQ)   // 4096
#define WIN    128
#define QB     64

// ---------------- scratch (device globals) -------------------------------------
__device__ float g_Q[BATCH*NH*SEQ*HD];
__device__ float g_K[BATCH*NH*SEQ*HD];
__device__ float g_V[BATCH*NH*SEQ*HD];
__device__ float g_At[MTOT*HIDDEN];     // tf32-rounded activations
__device__ float g_Wq[HIDDEN*HIDDEN];   // tf32-rounded weights
__device__ float g_Wk[HIDDEN*HIDDEN];
__device__ float g_Wv[HIDDEN*HIDDEN];
__device__ float g_Wo[HIDDEN*HIDDEN];

// ---------------- helpers -------------------------------------------------------
__device__ __forceinline__ uint32_t smem_u32(const void* p) {
    uint32_t a;
    asm("{ .reg .u64 t; cvta.to.shared.u64 t, %1; cvt.u32.u64 %0, t; }" : "=r"(a) : "l"(p));
    return a;
}
__device__ __forceinline__ float tf32r(float x) {
    uint32_t y;
    asm("cvt.rna.tf32.f32 %0, %1;" : "=r"(y) : "f"(x));
    return __uint_as_float(y);
}
__device__ __forceinline__ void cp16(uint32_t dst, const float* src) {
    asm volatile("cp.async.cg.shared.global [%0], [%1], 16;" :: "r"(dst), "l"(src) : "memory");
}
__device__ __forceinline__ void cp16z(uint32_t dst, const float* src, int srcsz) {
    asm volatile("cp.async.cg.shared.global [%0], [%1], 16, %2;"
                 :: "r"(dst), "l"(src), "r"(srcsz) : "memory");
}
#define CP_COMMIT() asm volatile("cp.async.commit_group;" ::: "memory")
#define CP_WAIT2()  asm volatile("cp.async.wait_group 2;" ::: "memory")
#define CP_WAIT0()  asm volatile("cp.async.wait_group 0;" ::: "memory")

__device__ __forceinline__ void mma_tf32(float* d, const uint32_t* a, const uint32_t* b) {
    asm volatile("mma.sync.aligned.m16n8k8.row.col.f32.tf32.tf32.f32 "
        "{%0,%1,%2,%3}, {%4,%5,%6,%7}, {%8,%9}, {%0,%1,%2,%3};"
        : "+f"(d[0]), "+f"(d[1]), "+f"(d[2]), "+f"(d[3])
        : "r"(a[0]), "r"(a[1]), "r"(a[2]), "r"(a[3]), "r"(b[0]), "r"(b[1]));
}

// ---------------- tf32 GEMM: 128x256 tile, 64x64 warp tile, pre-rounded ops ------
#define BM 128
#define BN 256
#define BK 32
#define STAGES 4
#define AS_STRIDE 36
#define BS_STRIDE 260
#define A_STAGE (BM*AS_STRIDE)             // 4608
#define B_STAGE (BK*BS_STRIDE)             // 8320
#define STAGE_FLOATS (A_STAGE + B_STAGE)   // 12928
#define GEMM_SMEM (STAGES*STAGE_FLOATS*4)  // 206848 B (1 CTA/SM)

__global__ __launch_bounds__(256, 1) void gemm_mma_kernel(
    const float* __restrict__ A,
    const float* __restrict__ W0, const float* __restrict__ W1, const float* __restrict__ W2,
    const float* __restrict__ bias0, const float* __restrict__ bias1, const float* __restrict__ bias2,
    float* __restrict__ out0, float* __restrict__ out1, float* __restrict__ out2,
    int mode)
{
    extern __shared__ float sm[];
    const int tid  = threadIdx.x;
    const int lane = tid & 31;
    const int wid  = tid >> 5;
    const int n0 = blockIdx.x * BN;
    const int m0 = blockIdx.y * BM;
    const int z  = blockIdx.z;

    const float* W    = (z == 0) ? W0 : (z == 1) ? W1 : W2;
    const float* bias = (z == 0) ? bias0 : (z == 1) ? bias1 : bias2;
    float* out        = (z == 0) ? out0 : (z == 1) ? out1 : out2;

    const int wm = (wid & 1) * 64;
    const int wn = (wid >> 1) * 64;

    float d[4][8][4];
#pragma unroll
    for (int mi = 0; mi < 4; mi++)
#pragma unroll
        for (int ni = 0; ni < 8; ni++)
#pragma unroll
            for (int c = 0; c < 4; c++) d[mi][ni][c] = 0.f;

    const uint32_t sb = smem_u32(sm);

    auto load_stage = [&](int kt, int s) {
        const uint32_t a_off = sb + (uint32_t)(s * STAGE_FLOATS) * 4u;
        const uint32_t b_off = a_off + A_STAGE * 4u;
        const float* Ag = A + (long)m0 * HIDDEN + kt * BK;
        const float* Wg = W + (long)(kt * BK) * HIDDEN + n0;
#pragma unroll
        for (int rep = 0; rep < 4; rep++) {
            int lin = rep * 256 + tid;
            int ar = lin >> 3, aq = lin & 7;
            cp16(a_off + (uint32_t)(ar * AS_STRIDE + aq * 4) * 4u,
                 Ag + (long)ar * HIDDEN + aq * 4);
        }
#pragma unroll
        for (int rep = 0; rep < 8; rep++) {
            int lin = rep * 256 + tid;
            int br = lin >> 6, bq = lin & 63;
            cp16(b_off + (uint32_t)(br * BS_STRIDE + bq * 4) * 4u,
                 Wg + (long)br * HIDDEN + bq * 4);
        }
        CP_COMMIT();
    };

    load_stage(0, 0);
    load_stage(1, 1);
    load_stage(2, 2);

    const int lg = lane >> 2;
    const int lt = lane & 3;

    for (int kt = 0; kt < HIDDEN / BK; kt++) {
        const int s = kt & (STAGES - 1);
        CP_WAIT2();
        __syncthreads();
        if (kt + 3 < HIDDEN / BK) load_stage(kt + 3, (kt + 3) & (STAGES - 1));
        else CP_COMMIT();

        const float* As = sm + s * STAGE_FLOATS;
        const float* Bs = As + A_STAGE;

#pragma unroll
        for (int k8 = 0; k8 < 4; k8++) {
            const int kb = k8 * 8;
            uint32_t a[4][4];
#pragma unroll
            for (int mi = 0; mi < 4; mi++) {
                const float* ap = As + (wm + mi * 16 + lg) * AS_STRIDE + kb + lt;
                a[mi][0] = __float_as_uint(ap[0]);
                a[mi][1] = __float_as_uint(ap[8 * AS_STRIDE]);
                a[mi][2] = __float_as_uint(ap[4]);
                a[mi][3] = __float_as_uint(ap[8 * AS_STRIDE + 4]);
            }
#pragma unroll
            for (int ni = 0; ni < 8; ni++) {
                uint32_t bb[2];
                const float* bp = Bs + (kb + lt) * BS_STRIDE + wn + ni * 8 + lg;
                bb[0] = __float_as_uint(bp[0]);
                bb[1] = __float_as_uint(bp[4 * BS_STRIDE]);
#pragma unroll
                for (int mi = 0; mi < 4; mi++)
                    mma_tf32(d[mi][ni], a[mi], bb);
            }
        }
    }

#pragma unroll
    for (int mi = 0; mi < 4; mi++) {
#pragma unroll
        for (int rh = 0; rh < 2; rh++) {
            const int row = m0 + wm + mi * 16 + lg + rh * 8;
            const int bb = row >> 11;
            const int ss = row & (SEQ - 1);
#pragma unroll
            for (int ni = 0; ni < 8; ni++) {
                const int col = n0 + wn + ni * 8 + lt * 2;
                float2 v;
                v.x = d[mi][ni][rh * 2 + 0] + __ldg(&bias[col]);
                v.y = d[mi][ni][rh * 2 + 1] + __ldg(&bias[col + 1]);
                if (mode == 0) {
                    const int h  = col >> 6;
                    const int dd = col & 63;
                    *(float2*)&out[(((long)(bb * NH + h) * SEQ) + ss) * HD + dd] = v;
                } else {
                    *(float2*)&out[(long)row * HIDDEN + col] = v;
                }
            }
        }
    }
}

// ---------------- tf32 rounding kernels -------------------------------------------
__global__ void cvt_kernel(const float4* __restrict__ in, float4* __restrict__ out, int n4) {
    int i = blockIdx.x * blockDim.x + threadIdx.x;
    if (i < n4) {
        float4 v = in[i];
        v.x = tf32r(v.x); v.y = tf32r(v.y); v.z = tf32r(v.z); v.w = tf32r(v.w);
        out[i] = v;
    }
}
__global__ void cvtw_kernel(const float4* __restrict__ w0, const float4* __restrict__ w1,
                            const float4* __restrict__ w2, const float4* __restrict__ w3,
                            float4* __restrict__ o0, float4* __restrict__ o1,
                            float4* __restrict__ o2, float4* __restrict__ o3) {
    const int z = blockIdx.y;
    const float4* in = (z == 0) ? w0 : (z == 1) ? w1 : (z == 2) ? w2 : w3;
    float4* out      = (z == 0) ? o0 : (z == 1) ? o1 : (z == 2) ? o2 : o3;
    int i = blockIdx.x * blockDim.x + threadIdx.x;
    float4 v = in[i];
    v.x = tf32r(v.x); v.y = tf32r(v.y); v.z = tf32r(v.z); v.w = tf32r(v.w);
    out[i] = v;
}

// ---------------- chunked attention (R7/R8 version, rounded output) ---------------
#define CH   160
#define SQ   68
#define SKN  68
#define SVC  72
#define SPC  164
#define SO   66
#define QS_OFF  0
#define KS_OFF  4352
#define VS_OFF  (KS_OFF + CH*SKN)
#define RED_OFF (VS_OFF + CH*SVC)
#define ATTN_FLOATS (RED_OFF + 128)
#define ATTN_SMEM (ATTN_FLOATS * 4)

__global__ __launch_bounds__(256, 2) void attn_mma_kernel(
    const float* __restrict__ Q, const float* __restrict__ K,
    const float* __restrict__ V, float* __restrict__ O)
{
    extern __shared__ float sm[];
    float* Qs = sm + QS_OFF;
    float* Ks = sm + KS_OFF;
    float* Vs = sm + VS_OFF;
    float* red = sm + RED_OFF;

    const int q0 = blockIdx.x * QB;
    const int h  = blockIdx.y;
    const int b  = blockIdx.z;
    const int tid = threadIdx.x;
    const long base = ((long)(b * NH + h)) * SEQ * HD;
    const float* Kb = K + base;
    const float* Vb = V + base;
    const float* Qb = Q + base;
    const int j0 = q0 - WIN;

    const uint32_t sb = smem_u32(sm);
    const int lane = tid & 31;
    const int wid  = tid >> 5;
    const int lg = lane >> 2;
    const int lt = lane & 3;
    const int wm = (wid & 3) * 16;
    const int half = wid >> 2;
    const int wn = half * 80;
    const float scale = 0.125f;

    for (int idx = tid; idx < 64 * 16; idx += 256) {
        int r = idx >> 4, c4 = (idx & 15) << 2;
        float4 v = *(const float4*)&Qb[(long)(q0 + r) * HD + c4];
        v.x = tf32r(v.x); v.y = tf32r(v.y); v.z = tf32r(v.z); v.w = tf32r(v.w);
        *(float4*)&Qs[r * SQ + c4] = v;
    }

    float o[8][4];
#pragma unroll
    for (int nt = 0; nt < 8; nt++) { o[nt][0] = 0.f; o[nt][1] = 0.f; o[nt][2] = 0.f; o[nt][3] = 0.f; }
    float sum0 = 0.f, sum1 = 0.f;

    const int r0 = q0 + wm + lg;
    const int r1 = r0 + 8;
    const int lo0 = ((r0 - WIN > 0) ? r0 - WIN : 0) - j0;
    const int hi0 = ((r0 + WIN < SEQ - 1) ? r0 + WIN : SEQ - 1) - j0;
    const int lo1 = ((r1 - WIN > 0) ? r1 - WIN : 0) - j0;
    const int hi1 = ((r1 + WIN < SEQ - 1) ? r1 + WIN : SEQ - 1) - j0;

    uint32_t a[8][4];
    bool afrag_loaded = false;

#pragma unroll
    for (int ch = 0; ch < 2; ch++) {
        const int cb = ch * CH;

        {
            const int rb = tid >> 4;
            const int cq = (tid & 15) << 2;
#pragma unroll
            for (int r10 = 0; r10 < 10; r10++) {
                const int jj = r10 * 16 + rb;
                const int j  = j0 + cb + jj;
                const int ok = (j >= 0 && j < SEQ) ? 16 : 0;
                cp16z(sb + (uint32_t)(KS_OFF + jj * SKN + cq) * 4u, Kb + (long)j * HD + cq, ok);
                cp16z(sb + (uint32_t)(VS_OFF + jj * SVC + cq) * 4u, Vb + (long)j * HD + cq, ok);
            }
            CP_COMMIT();
        }
        CP_WAIT0();
        __syncthreads();

        if (!afrag_loaded) {
            afrag_loaded = true;
#pragma unroll
            for (int k8 = 0; k8 < 8; k8++) {
                const float* ap = Qs + (wm + lg) * SQ + k8 * 8 + lt;
                a[k8][0] = __float_as_uint(ap[0]);
                a[k8][1] = __float_as_uint(ap[8 * SQ]);
                a[k8][2] = __float_as_uint(ap[4]);
                a[k8][3] = __float_as_uint(ap[8 * SQ + 4]);
            }
        }

        float c[10][4];
#pragma unroll
        for (int nt = 0; nt < 10; nt++) {
            c[nt][0] = 0.f; c[nt][1] = 0.f; c[nt][2] = 0.f; c[nt][3] = 0.f;
            const int key = wn + nt * 8 + lg;
            const float* kp = Ks + key * SKN + lt;
#pragma unroll
            for (int k8 = 0; k8 < 8; k8++) {
                uint32_t bb[2];
                bb[0] = __float_as_uint(tf32r(kp[k8 * 8]));
                bb[1] = __float_as_uint(tf32r(kp[k8 * 8 + 4]));
                mma_tf32(c[nt], a[k8], bb);
            }
        }

#pragma unroll
        for (int nt = 0; nt < 10; nt++) {
            const int jw = cb + wn + nt * 8 + 2 * lt;
            float p0 = (jw     >= lo0 && jw     <= hi0) ? tf32r(__expf(c[nt][0] * scale)) : 0.f;
            float p1 = (jw + 1 >= lo0 && jw + 1 <= hi0) ? tf32r(__expf(c[nt][1] * scale)) : 0.f;
            float p2 = (jw     >= lo1 && jw     <= hi1) ? tf32r(__expf(c[nt][2] * scale)) : 0.f;
            float p3 = (jw + 1 >= lo1 && jw + 1 <= hi1) ? tf32r(__expf(c[nt][3] * scale)) : 0.f;
            c[nt][0] = p0; c[nt][1] = p1; c[nt][2] = p2; c[nt][3] = p3;
            sum0 += p0 + p1;
            sum1 += p2 + p3;
        }

        __syncthreads();

        float* Ps = Ks;
#pragma unroll
        for (int nt = 0; nt < 10; nt++) {
            const int col = wn + nt * 8 + 2 * lt;
            *(float2*)&Ps[(wm + lg) * SPC + col]     = make_float2(c[nt][0], c[nt][1]);
            *(float2*)&Ps[(wm + lg + 8) * SPC + col] = make_float2(c[nt][2], c[nt][3]);
        }
        __syncthreads();

#pragma unroll
        for (int k8 = 0; k8 < 10; k8++) {
            const int kk = wn + k8 * 8;
            uint32_t a2[4];
            const float* ap = Ps + (wm + lg) * SPC + kk + lt;
            a2[0] = __float_as_uint(ap[0]);
            a2[1] = __float_as_uint(ap[8 * SPC]);
            a2[2] = __float_as_uint(ap[4]);
            a2[3] = __float_as_uint(ap[8 * SPC + 4]);
#pragma unroll
            for (int nt = 0; nt < 8; nt++) {
                uint32_t bb[2];
                const float* bp = Vs + (kk + lt) * SVC + nt * 8 + lg;
                bb[0] = __float_as_uint(bp[0]);
                bb[1] = __float_as_uint(bp[4 * SVC]);
                mma_tf32(o[nt], a2, bb);
            }
        }
        __syncthreads();
    }

    sum0 += __shfl_xor_sync(0xffffffffu, sum0, 1);
    sum0 += __shfl_xor_sync(0xffffffffu, sum0, 2);
    sum1 += __shfl_xor_sync(0xffffffffu, sum1, 1);
    sum1 += __shfl_xor_sync(0xffffffffu, sum1, 2);
    if (lt == 0) {
        red[half * 64 + wm + lg]     = sum0;
        red[half * 64 + wm + lg + 8] = sum1;
    }

    float* obuf = Qs;
    if (half == 0) {
#pragma unroll
        for (int nt = 0; nt < 8; nt++) {
            const int col = nt * 8 + 2 * lt;
            *(float2*)&obuf[(wm + lg) * SO + col]     = make_float2(o[nt][0], o[nt][1]);
            *(float2*)&obuf[(wm + lg + 8) * SO + col] = make_float2(o[nt][2], o[nt][3]);
        }
    }
    __syncthreads();
    if (half == 1) {
        const float inv0 = 1.f / (red[wm + lg] + red[64 + wm + lg]);
        const float inv1 = 1.f / (red[wm + lg + 8] + red[64 + wm + lg + 8]);
        const long ob0 = ((long)(b * SEQ + r0)) * HIDDEN + h * HD;
        const long ob1 = ((long)(b * SEQ + r1)) * HIDDEN + h * HD;
#pragma unroll
        for (int nt = 0; nt < 8; nt++) {
            const int col = nt * 8 + 2 * lt;
            float2 u0 = *(const float2*)&obuf[(wm + lg) * SO + col];
            float2 u1 = *(const float2*)&obuf[(wm + lg + 8) * SO + col];
            float2 w0, w1;
            w0.x = tf32r((o[nt][0] + u0.x) * inv0);
            w0.y = tf32r((o[nt][1] + u0.y) * inv0);
            w1.x = tf32r((o[nt][2] + u1.x) * inv1);
            w1.y = tf32r((o[nt][3] + u1.y) * inv1);
            *(float2*)&O[ob0 + col] = w0;
            *(float2*)&O[ob1 + col] = w1;
        }
    }
}

// ---------------- launcher --------------------------------------------------------
extern "C" void kernel_launch(void* const* d_in, const int* in_sizes, int n_in,
                              void* d_out, int out_size)
{
    const float* x  = (const float*)d_in[0];
    const float* wq = (const float*)d_in[1];
    const float* bq = (const float*)d_in[2];
    const float* wk = (const float*)d_in[3];
    const float* bk = (const float*)d_in[4];
    const float* wv = (const float*)d_in[5];
    const float* bv = (const float*)d_in[6];
    const float* wo = (const float*)d_in[7];
    const float* bo = (const float*)d_in[8];

    float *gq, *gk, *gv, *gat, *gwq, *gwk, *gwv, *gwo;
    cudaGetSymbolAddress((void**)&gq,  g_Q);
    cudaGetSymbolAddress((void**)&gk,  g_K);
    cudaGetSymbolAddress((void**)&gv,  g_V);
    cudaGetSymbolAddress((void**)&gat, g_At);
    cudaGetSymbolAddress((void**)&gwq, g_Wq);
    cudaGetSymbolAddress((void**)&gwk, g_Wk);
    cudaGetSymbolAddress((void**)&gwv, g_Wv);
    cudaGetSymbolAddress((void**)&gwo, g_Wo);

    cudaFuncSetAttribute(gemm_mma_kernel,
                         cudaFuncAttributeMaxDynamicSharedMemorySize, GEMM_SMEM);
    cudaFuncSetAttribute(attn_mma_kernel,
                         cudaFuncAttributeMaxDynamicSharedMemorySize, ATTN_SMEM);

    const int n4a = MTOT * HIDDEN / 4;
    const int n4w = HIDDEN * HIDDEN / 4;

    // pre-round x + weights (rna, unbiased)
    cvt_kernel<<<(n4a + 255) / 256, 256>>>((const float4*)x, (float4*)gat, n4a);
    {
        dim3 g(n4w / 256, 4);
        cvtw_kernel<<<g, 256>>>((const float4*)wq, (const float4*)wk,
                                (const float4*)wv, (const float4*)wo,
                                (float4*)gwq, (float4*)gwk, (float4*)gwv, (float4*)gwo);
    }
    {   // fused QKV projections (pre-rounded operands, no in-loop cvt)
        dim3 g(HIDDEN / BN, MTOT / BM, 3);
        gemm_mma_kernel<<<g, 256, GEMM_SMEM>>>(gat, gwq, gwk, gwv,
                                               bq, bk, bv, gq, gk, gv, 0);
    }
    {   // chunked MMA attention -> tf32-rounded output into g_At
        dim3 ga(SEQ / QB, NH, BATCH);
        attn_mma_kernel<<<ga, 256, ATTN_SMEM>>>(gq, gk, gv, gat);
    }
    {   // output projection
        dim3 g(HIDDEN / BN, MTOT / BM, 1);
        gemm_mma_kernel<<<g, 256, GEMM_SMEM>>>(gat, gwo, gwo, gwo,
                                               bo, bo, bo, (float*)d_out,
                                               (float*)d_out, (float*)d_out, 1);
    }
}